// round 1
// baseline (speedup 1.0000x reference)
#include <cuda_runtime.h>
#include <math.h>

// ---------------------------------------------------------------------------
// Problem constants
// ---------------------------------------------------------------------------
#define BATCH 2
#define SEQ   2048
#define EMB   1024
#define HEADS 16
#define HDIM  64
#define MROWS (BATCH * SEQ)        // 4096

// Scratch (no cudaMalloc allowed)
__device__ float g_qkv[MROWS * 3 * EMB];   // [B*S, 3E]  ~50 MB
__device__ float g_ctx[MROWS * EMB];       // [B*S, E]   ~17 MB

// ---------------------------------------------------------------------------
// SGEMM NT:  C[M,N] = A[M,K] @ B[N,K]^T + bias[N]
//   A row-major [M,K], B row-major [N,K] (both K contiguous)
//   BM=BN=128, BK=16, 256 threads, 8x8 microtile per thread
// ---------------------------------------------------------------------------
#define GBM 128
#define GBN 128
#define GBK 16
#define GPAD 4

__global__ __launch_bounds__(256, 2)
void sgemm_nt_kernel(const float* __restrict__ A,
                     const float* __restrict__ B,
                     const float* __restrict__ bias,
                     float* __restrict__ C,
                     int M, int N, int K)
{
    __shared__ float As[GBK][GBM + GPAD];
    __shared__ float Bs[GBK][GBN + GPAD];

    const int tid = threadIdx.x;
    const int tx  = tid & 15;          // 16 thread cols
    const int ty  = tid >> 4;          // 16 thread rows
    const int m0  = blockIdx.y * GBM;
    const int n0  = blockIdx.x * GBN;

    float acc[8][8];
#pragma unroll
    for (int i = 0; i < 8; i++)
#pragma unroll
        for (int j = 0; j < 8; j++) acc[i][j] = 0.0f;

    for (int k0 = 0; k0 < K; k0 += GBK) {
        // load A tile: 128 rows x 16 cols = 512 float4, 2 per thread
#pragma unroll
        for (int r = 0; r < 2; r++) {
            int idx = tid + r * 256;
            int row = idx >> 2;            // 0..127
            int vec = idx & 3;             // 0..3
            float4 va = *(const float4*)&A[(size_t)(m0 + row) * K + k0 + vec * 4];
            As[vec * 4 + 0][row] = va.x;
            As[vec * 4 + 1][row] = va.y;
            As[vec * 4 + 2][row] = va.z;
            As[vec * 4 + 3][row] = va.w;
        }
        // load B tile: 128 rows x 16 cols
#pragma unroll
        for (int r = 0; r < 2; r++) {
            int idx = tid + r * 256;
            int row = idx >> 2;
            int vec = idx & 3;
            float4 vb = *(const float4*)&B[(size_t)(n0 + row) * K + k0 + vec * 4];
            Bs[vec * 4 + 0][row] = vb.x;
            Bs[vec * 4 + 1][row] = vb.y;
            Bs[vec * 4 + 2][row] = vb.z;
            Bs[vec * 4 + 3][row] = vb.w;
        }
        __syncthreads();

#pragma unroll
        for (int k = 0; k < GBK; k++) {
            float4 a0 = *(const float4*)&As[k][ty * 8];
            float4 a1 = *(const float4*)&As[k][ty * 8 + 4];
            float4 b0 = *(const float4*)&Bs[k][tx * 8];
            float4 b1 = *(const float4*)&Bs[k][tx * 8 + 4];
            float a[8] = {a0.x, a0.y, a0.z, a0.w, a1.x, a1.y, a1.z, a1.w};
            float b[8] = {b0.x, b0.y, b0.z, b0.w, b1.x, b1.y, b1.z, b1.w};
#pragma unroll
            for (int i = 0; i < 8; i++)
#pragma unroll
                for (int j = 0; j < 8; j++)
                    acc[i][j] = fmaf(a[i], b[j], acc[i][j]);
        }
        __syncthreads();
    }

    // epilogue with bias
    float bsv[8];
#pragma unroll
    for (int j = 0; j < 8; j++) bsv[j] = bias[n0 + tx * 8 + j];

#pragma unroll
    for (int i = 0; i < 8; i++) {
        int row = m0 + ty * 8 + i;
        float* crow = &C[(size_t)row * N + n0 + tx * 8];
        float4 o0 = make_float4(acc[i][0] + bsv[0], acc[i][1] + bsv[1],
                                acc[i][2] + bsv[2], acc[i][3] + bsv[3]);
        float4 o1 = make_float4(acc[i][4] + bsv[4], acc[i][5] + bsv[5],
                                acc[i][6] + bsv[6], acc[i][7] + bsv[7]);
        *(float4*)&crow[0] = o0;
        *(float4*)&crow[4] = o1;
    }
}

// ---------------------------------------------------------------------------
// Flash attention (fp32). One CTA handles 64 query rows for one (b,h).
// Online softmax over 64-key tiles. 256 threads, 4x4 microtiles.
// ctx written as [B,S,E] so the out-proj GEMM reads it directly.
// ---------------------------------------------------------------------------
#define BQ  64
#define BKV 64
#define APAD 4
#define AQ_LD (BQ + APAD)
#define AD_LD (HDIM + APAD)

__global__ __launch_bounds__(256, 2)
void attn_kernel(const float* __restrict__ qkv,
                 const float* __restrict__ mask,
                 float* __restrict__ ctx)
{
    extern __shared__ float sm[];
    float* Qs = sm;                          // [HDIM][AQ_LD]  (d-major, transposed)
    float* Ks = Qs + HDIM * AQ_LD;           // [HDIM][AQ_LD]  (d-major, transposed)
    float* Vs = Ks + HDIM * AQ_LD;           // [BKV][AD_LD]   (natural)
    float* Ps = Vs + BKV * AD_LD;            // [BQ][AQ_LD]    (natural: [i][j])

    const int qt = blockIdx.x;               // query tile 0..31
    const int h  = blockIdx.y;               // 0..15
    const int b  = blockIdx.z;               // 0..1
    const int tid = threadIdx.x;
    const int tx  = tid & 15;
    const int ty  = tid >> 4;

    const int q0 = qt * BQ;
    const float scale = 0.125f;              // 1/sqrt(64)
    const size_t rowstride = 3 * EMB;
    const float* qbase = qkv + (size_t)b * SEQ * rowstride + h * HDIM;
    const float* kbase = qbase + EMB;
    const float* vbase = qbase + 2 * EMB;

    // load Q tile transposed (pre-scaled): Qs[d][i] = Q[q0+i][d] * scale
    {
        int row = tid >> 2;                  // 0..63
        int c0  = (tid & 3) * 16;            // 0,16,32,48
        const float* src = qbase + (size_t)(q0 + row) * rowstride;
#pragma unroll
        for (int c = 0; c < 4; c++) {
            float4 v = *(const float4*)&src[c0 + c * 4];
            int d = c0 + c * 4;
            Qs[(d + 0) * AQ_LD + row] = v.x * scale;
            Qs[(d + 1) * AQ_LD + row] = v.y * scale;
            Qs[(d + 2) * AQ_LD + row] = v.z * scale;
            Qs[(d + 3) * AQ_LD + row] = v.w * scale;
        }
    }

    float m_i[4], l_i[4], acc[4][4];
#pragma unroll
    for (int i = 0; i < 4; i++) {
        m_i[i] = -INFINITY;
        l_i[i] = 0.0f;
#pragma unroll
        for (int j = 0; j < 4; j++) acc[i][j] = 0.0f;
    }

    for (int kv0 = 0; kv0 < SEQ; kv0 += BKV) {
        __syncthreads();   // protect Ks/Vs/Ps from previous iteration readers

        // load K (transposed) and V (natural)
        {
            int row = tid >> 2;
            int c0  = (tid & 3) * 16;
            const float* ksrc = kbase + (size_t)(kv0 + row) * rowstride;
            const float* vsrc = vbase + (size_t)(kv0 + row) * rowstride;
#pragma unroll
            for (int c = 0; c < 4; c++) {
                int d = c0 + c * 4;
                float4 kv = *(const float4*)&ksrc[d];
                Ks[(d + 0) * AQ_LD + row] = kv.x;
                Ks[(d + 1) * AQ_LD + row] = kv.y;
                Ks[(d + 2) * AQ_LD + row] = kv.z;
                Ks[(d + 3) * AQ_LD + row] = kv.w;
                float4 vv = *(const float4*)&vsrc[d];
                *(float4*)&Vs[row * AD_LD + d] = vv;
            }
        }
        __syncthreads();

        // S = (Q*scale) @ K^T   (4x4 microtile: rows i=ty*4.., cols j=tx*4..)
        float s[4][4];
#pragma unroll
        for (int i = 0; i < 4; i++)
#pragma unroll
            for (int j = 0; j < 4; j++) s[i][j] = 0.0f;

#pragma unroll
        for (int d = 0; d < HDIM; d++) {
            float4 a = *(const float4*)&Qs[d * AQ_LD + ty * 4];
            float4 bb = *(const float4*)&Ks[d * AQ_LD + tx * 4];
            float av[4] = {a.x, a.y, a.z, a.w};
            float bv[4] = {bb.x, bb.y, bb.z, bb.w};
#pragma unroll
            for (int i = 0; i < 4; i++)
#pragma unroll
                for (int j = 0; j < 4; j++)
                    s[i][j] = fmaf(av[i], bv[j], s[i][j]);
        }

        // mask: s += mask[b][q][k] * (-10000)
#pragma unroll
        for (int i = 0; i < 4; i++) {
            const float4 mv = *(const float4*)&mask[((size_t)b * SEQ + q0 + ty * 4 + i) * SEQ
                                                    + kv0 + tx * 4];
            s[i][0] = fmaf(mv.x, -10000.0f, s[i][0]);
            s[i][1] = fmaf(mv.y, -10000.0f, s[i][1]);
            s[i][2] = fmaf(mv.z, -10000.0f, s[i][2]);
            s[i][3] = fmaf(mv.w, -10000.0f, s[i][3]);
        }

        // online softmax per query row (16 lanes share a row; xor-shuffle reduce)
#pragma unroll
        for (int i = 0; i < 4; i++) {
            float rm = fmaxf(fmaxf(s[i][0], s[i][1]), fmaxf(s[i][2], s[i][3]));
#pragma unroll
            for (int o = 1; o < 16; o <<= 1)
                rm = fmaxf(rm, __shfl_xor_sync(0xffffffff, rm, o));
            float mnew = fmaxf(m_i[i], rm);
            float corr = __expf(m_i[i] - mnew);
            float rs = 0.0f;
#pragma unroll
            for (int j = 0; j < 4; j++) {
                float p = __expf(s[i][j] - mnew);
                s[i][j] = p;
                rs += p;
            }
#pragma unroll
            for (int o = 1; o < 16; o <<= 1)
                rs += __shfl_xor_sync(0xffffffff, rs, o);
            l_i[i] = l_i[i] * corr + rs;
            m_i[i] = mnew;
#pragma unroll
            for (int j = 0; j < 4; j++) acc[i][j] *= corr;
        }

        // write P (natural layout [i][j]) with float4 stores
#pragma unroll
        for (int i = 0; i < 4; i++) {
            float4 pv = make_float4(s[i][0], s[i][1], s[i][2], s[i][3]);
            *(float4*)&Ps[(ty * 4 + i) * AQ_LD + tx * 4] = pv;
        }
        __syncthreads();

        // O += P @ V   (k-loop over j; P read as broadcast scalars, V as float4)
#pragma unroll 8
        for (int j = 0; j < BKV; j++) {
            float4 bb = *(const float4*)&Vs[j * AD_LD + tx * 4];
            float a0 = Ps[(ty * 4 + 0) * AQ_LD + j];
            float a1 = Ps[(ty * 4 + 1) * AQ_LD + j];
            float a2 = Ps[(ty * 4 + 2) * AQ_LD + j];
            float a3 = Ps[(ty * 4 + 3) * AQ_LD + j];
            float bv[4] = {bb.x, bb.y, bb.z, bb.w};
            float av[4] = {a0, a1, a2, a3};
#pragma unroll
            for (int i = 0; i < 4; i++)
#pragma unroll
                for (int jj = 0; jj < 4; jj++)
                    acc[i][jj] = fmaf(av[i], bv[jj], acc[i][jj]);
        }
    }

    // epilogue: ctx[b][q0+i][h*64 + d] = acc / l
#pragma unroll
    for (int i = 0; i < 4; i++) {
        float inv = 1.0f / l_i[i];
        float4 o = make_float4(acc[i][0] * inv, acc[i][1] * inv,
                               acc[i][2] * inv, acc[i][3] * inv);
        *(float4*)&ctx[((size_t)b * SEQ + q0 + ty * 4 + i) * EMB + h * HDIM + tx * 4] = o;
    }
}

// ---------------------------------------------------------------------------
// Launch
// ---------------------------------------------------------------------------
extern "C" void kernel_launch(void* const* d_in, const int* in_sizes, int n_in,
                              void* d_out, int out_size)
{
    const float* x     = (const float*)d_in[0];
    const float* mask  = (const float*)d_in[1];
    const float* w_in  = (const float*)d_in[2];
    const float* b_in  = (const float*)d_in[3];
    const float* w_out = (const float*)d_in[4];
    const float* b_out = (const float*)d_in[5];
    float* out = (float*)d_out;

    void* pq = nullptr;
    void* pc = nullptr;
    cudaGetSymbolAddress(&pq, g_qkv);
    cudaGetSymbolAddress(&pc, g_ctx);
    float* qkv = (float*)pq;
    float* ctx = (float*)pc;

    // attention kernel dynamic smem
    const int attn_smem = (2 * HDIM * AQ_LD + BKV * AD_LD + BQ * AQ_LD) * (int)sizeof(float);
    cudaFuncSetAttribute(attn_kernel, cudaFuncAttributeMaxDynamicSharedMemorySize, attn_smem);

    // 1) QKV projection: [4096,3072] = x[4096,1024] @ W_in[3072,1024]^T + b_in
    {
        dim3 grid(3 * EMB / GBN, MROWS / GBM);
        sgemm_nt_kernel<<<grid, 256>>>(x, w_in, b_in, qkv, MROWS, 3 * EMB, EMB);
    }

    // 2) attention -> ctx [B,S,E]
    {
        dim3 grid(SEQ / BQ, HEADS, BATCH);
        attn_kernel<<<grid, 256, attn_smem>>>(qkv, mask, ctx);
    }

    // 3) output projection: out[4096,1024] = ctx @ W_out^T + b_out
    {
        dim3 grid(EMB / GBN, MROWS / GBM);
        sgemm_nt_kernel<<<grid, 256>>>(ctx, w_out, b_out, out, MROWS, EMB, EMB);
    }
}

// round 3
// speedup vs baseline: 1.3538x; 1.3538x over previous
#include <cuda_runtime.h>
#include <cuda_bf16.h>
#include <math.h>
#include <stdint.h>

// ---------------------------------------------------------------------------
// Problem constants
// ---------------------------------------------------------------------------
#define BATCH 2
#define SEQ   2048
#define EMB   1024
#define HEADS 16
#define HDIM  64
#define MROWS (BATCH * SEQ)        // 4096

// Scratch (no cudaMalloc allowed)
__device__ float g_qkv[MROWS * 3 * EMB];   // [B*S, 3E]
__device__ float g_ctx[MROWS * EMB];       // [B*S, E]

// ---------------------------------------------------------------------------
// warp-MMA helpers (sm_80+ PTX — legal under compute_103; NO tcgen05)
// ---------------------------------------------------------------------------
__device__ __forceinline__ uint32_t smem_u32(const void* p) {
    uint32_t a;
    asm("{ .reg .u64 t; cvta.to.shared.u64 t, %1; cvt.u32.u64 %0, t; }"
        : "=r"(a) : "l"(p));
    return a;
}

__device__ __forceinline__ void ldsm4(uint32_t r[4], uint32_t addr) {
    asm volatile("ldmatrix.sync.aligned.m8n8.x4.shared.b16 {%0,%1,%2,%3}, [%4];"
                 : "=r"(r[0]), "=r"(r[1]), "=r"(r[2]), "=r"(r[3]) : "r"(addr));
}

__device__ __forceinline__ void ldsm2(uint32_t r[2], uint32_t addr) {
    asm volatile("ldmatrix.sync.aligned.m8n8.x2.shared.b16 {%0,%1}, [%2];"
                 : "=r"(r[0]), "=r"(r[1]) : "r"(addr));
}

__device__ __forceinline__ void mma16816(float d[4], const uint32_t a[4], const uint32_t b[2]) {
    asm volatile(
        "mma.sync.aligned.m16n8k16.row.col.f32.bf16.bf16.f32 "
        "{%0,%1,%2,%3}, {%4,%5,%6,%7}, {%8,%9}, {%0,%1,%2,%3};"
        : "+f"(d[0]), "+f"(d[1]), "+f"(d[2]), "+f"(d[3])
        : "r"(a[0]), "r"(a[1]), "r"(a[2]), "r"(a[3]), "r"(b[0]), "r"(b[1]));
}

// ---------------------------------------------------------------------------
// Tensor-core GEMM NT (bf16 hi/lo split, fp32 accumulate):
//   C[M,N] = A[M,K] @ B[N,K]^T + bias[N]
// 128x128 CTA tile, 8 warps (2x4 grid of 64x32 warp tiles), K chunk 32,
// double-buffered smem (pitch-40 bf16 rows for conflict-free ldmatrix).
// ---------------------------------------------------------------------------
#define PITCH 40                       // bf16 elems per smem row (80B)
#define TSZ   (128 * PITCH)            // elems per tile buffer
#define TSZB  (TSZ * 2)                // bytes per tile buffer
#define STAGEB (4 * TSZB)              // Ah,Al,Bh,Bl per stage
#define GSMEM  (2 * STAGEB)            // 81920 B

__device__ __forceinline__ void cvt_store8(float4 v, __nv_bfloat16* smem_base,
                                           uint32_t elem_off) {
    __nv_bfloat162 h01 = __float22bfloat162_rn(make_float2(v.x, v.y));
    __nv_bfloat162 h23 = __float22bfloat162_rn(make_float2(v.z, v.w));
    float2 f01 = __bfloat1622float2(h01);
    float2 f23 = __bfloat1622float2(h23);
    __nv_bfloat162 l01 = __float22bfloat162_rn(make_float2(v.x - f01.x, v.y - f01.y));
    __nv_bfloat162 l23 = __float22bfloat162_rn(make_float2(v.z - f23.x, v.w - f23.y));
    // hi at elem_off, lo at elem_off + TSZ
    uint2 hv, lv;
    hv.x = *(uint32_t*)&h01; hv.y = *(uint32_t*)&h23;
    lv.x = *(uint32_t*)&l01; lv.y = *(uint32_t*)&l23;
    *(uint2*)(smem_base + elem_off)       = hv;
    *(uint2*)(smem_base + elem_off + TSZ) = lv;
}

__global__ void __launch_bounds__(256, 1)
gemm_mma_kernel(const float* __restrict__ A,
                const float* __restrict__ B,
                const float* __restrict__ bias,
                float* __restrict__ C,
                int M, int N, int K)
{
    extern __shared__ __nv_bfloat16 smem[];
    const uint32_t sb = smem_u32(smem);

    const int tid  = threadIdx.x;
    const int lane = tid & 31;
    const int warp = tid >> 5;
    const int wm   = warp & 1;          // 0..1  (M)
    const int wn   = warp >> 1;         // 0..3  (N)
    const int m0   = blockIdx.y * 128;
    const int n0   = blockIdx.x * 128;

    float acc[4][4][4];
#pragma unroll
    for (int mi = 0; mi < 4; mi++)
#pragma unroll
        for (int ni = 0; ni < 4; ni++)
#pragma unroll
            for (int f = 0; f < 4; f++) acc[mi][ni][f] = 0.0f;

    // per-thread global-load geometry: 4 float4 each for A and B per chunk
    int lrow[4], lcol[4];
#pragma unroll
    for (int i = 0; i < 4; i++) {
        int idx = tid + i * 256;       // 0..1023
        lrow[i] = idx >> 3;            // 0..127
        lcol[i] = (idx & 7) * 4;       // 0..28
    }

    const int nch = K / 32;
    float4 ra[4], rb[4];

    // prologue: chunk 0
#pragma unroll
    for (int i = 0; i < 4; i++) {
        ra[i] = *(const float4*)(A + (size_t)(m0 + lrow[i]) * K + lcol[i]);
        rb[i] = *(const float4*)(B + (size_t)(n0 + lrow[i]) * K + lcol[i]);
    }
    {
        __nv_bfloat16* st = smem;      // stage 0
#pragma unroll
        for (int i = 0; i < 4; i++) {
            uint32_t off = lrow[i] * PITCH + lcol[i];
            cvt_store8(ra[i], st, off);                 // Ah/Al
            cvt_store8(rb[i], st + 2 * TSZ, off);       // Bh/Bl
        }
    }
    __syncthreads();

    // fragment addressing (stage-relative, bytes)
    const int arow  = lane & 15;
    const int acolb = (lane >> 4) * 8;          // 0 or 8 elems
    const int brow  = lane & 7;
    const int bcolb = ((lane >> 3) & 1) * 8;    // 0 or 8 elems

    for (int c = 0; c < nch; c++) {
        // issue next chunk's global loads (overlap with MMA below)
        if (c + 1 < nch) {
            const float* Ap = A + (size_t)m0 * K + (c + 1) * 32;
            const float* Bp = B + (size_t)n0 * K + (c + 1) * 32;
#pragma unroll
            for (int i = 0; i < 4; i++) {
                ra[i] = *(const float4*)(Ap + (size_t)lrow[i] * K + lcol[i]);
                rb[i] = *(const float4*)(Bp + (size_t)lrow[i] * K + lcol[i]);
            }
        }

        // compute chunk c from stage c&1
        const uint32_t stg = sb + (uint32_t)(c & 1) * STAGEB;
#pragma unroll
        for (int ks = 0; ks < 2; ks++) {
            uint32_t ah[4][4], al[4][4];
            const uint32_t acol = ks * 16 + acolb;
#pragma unroll
            for (int mi = 0; mi < 4; mi++) {
                uint32_t ad = stg + ((wm * 64 + mi * 16 + arow) * PITCH + acol) * 2;
                ldsm4(ah[mi], ad);
                ldsm4(al[mi], ad + TSZB);
            }
            const uint32_t bcol = ks * 16 + bcolb;
#pragma unroll
            for (int ni = 0; ni < 4; ni++) {
                uint32_t bd = stg + 2 * TSZB + ((wn * 32 + ni * 8 + brow) * PITCH + bcol) * 2;
                uint32_t bh[2], bl[2];
                ldsm2(bh, bd);
                ldsm2(bl, bd + TSZB);
#pragma unroll
                for (int mi = 0; mi < 4; mi++) {
                    mma16816(acc[mi][ni], ah[mi], bh);
                    mma16816(acc[mi][ni], ah[mi], bl);
                    mma16816(acc[mi][ni], al[mi], bh);
                }
            }
        }

        // store next chunk into the other stage
        if (c + 1 < nch) {
            __nv_bfloat16* st = smem + ((c + 1) & 1) * (STAGEB / 2);
#pragma unroll
            for (int i = 0; i < 4; i++) {
                uint32_t off = lrow[i] * PITCH + lcol[i];
                cvt_store8(ra[i], st, off);
                cvt_store8(rb[i], st + 2 * TSZ, off);
            }
            __syncthreads();
        }
    }

    // epilogue: fragment layout d0,d1 -> row l/4, cols 2*(l%4); d2,d3 -> row+8
    const int erow = lane >> 2;
    const int ecol = (lane & 3) * 2;
#pragma unroll
    for (int mi = 0; mi < 4; mi++) {
        int r0 = m0 + wm * 64 + mi * 16 + erow;
#pragma unroll
        for (int ni = 0; ni < 4; ni++) {
            int cc = n0 + wn * 32 + ni * 8 + ecol;
            float b0 = bias[cc], b1 = bias[cc + 1];
            float2 v0 = make_float2(acc[mi][ni][0] + b0, acc[mi][ni][1] + b1);
            float2 v1 = make_float2(acc[mi][ni][2] + b0, acc[mi][ni][3] + b1);
            *(float2*)(C + (size_t)r0 * N + cc)       = v0;
            *(float2*)(C + (size_t)(r0 + 8) * N + cc) = v1;
        }
    }
}

// ---------------------------------------------------------------------------
// Flash attention (fp32) — unchanged from round 1 (passing)
// ---------------------------------------------------------------------------
#define BQ  64
#define BKV 64
#define APAD 4
#define AQ_LD (BQ + APAD)
#define AD_LD (HDIM + APAD)

__global__ __launch_bounds__(256, 2)
void attn_kernel(const float* __restrict__ qkv,
                 const float* __restrict__ mask,
                 float* __restrict__ ctx)
{
    extern __shared__ float sm[];
    float* Qs = sm;
    float* Ks = Qs + HDIM * AQ_LD;
    float* Vs = Ks + HDIM * AQ_LD;
    float* Ps = Vs + BKV * AD_LD;

    const int qt = blockIdx.x;
    const int h  = blockIdx.y;
    const int b  = blockIdx.z;
    const int tid = threadIdx.x;
    const int tx  = tid & 15;
    const int ty  = tid >> 4;

    const int q0 = qt * BQ;
    const float scale = 0.125f;
    const size_t rowstride = 3 * EMB;
    const float* qbase = qkv + (size_t)b * SEQ * rowstride + h * HDIM;
    const float* kbase = qbase + EMB;
    const float* vbase = qbase + 2 * EMB;

    {
        int row = tid >> 2;
        int c0  = (tid & 3) * 16;
        const float* src = qbase + (size_t)(q0 + row) * rowstride;
#pragma unroll
        for (int c = 0; c < 4; c++) {
            float4 v = *(const float4*)&src[c0 + c * 4];
            int d = c0 + c * 4;
            Qs[(d + 0) * AQ_LD + row] = v.x * scale;
            Qs[(d + 1) * AQ_LD + row] = v.y * scale;
            Qs[(d + 2) * AQ_LD + row] = v.z * scale;
            Qs[(d + 3) * AQ_LD + row] = v.w * scale;
        }
    }

    float m_i[4], l_i[4], acc[4][4];
#pragma unroll
    for (int i = 0; i < 4; i++) {
        m_i[i] = -INFINITY;
        l_i[i] = 0.0f;
#pragma unroll
        for (int j = 0; j < 4; j++) acc[i][j] = 0.0f;
    }

    for (int kv0 = 0; kv0 < SEQ; kv0 += BKV) {
        __syncthreads();
        {
            int row = tid >> 2;
            int c0  = (tid & 3) * 16;
            const float* ksrc = kbase + (size_t)(kv0 + row) * rowstride;
            const float* vsrc = vbase + (size_t)(kv0 + row) * rowstride;
#pragma unroll
            for (int c = 0; c < 4; c++) {
                int d = c0 + c * 4;
                float4 kv = *(const float4*)&ksrc[d];
                Ks[(d + 0) * AQ_LD + row] = kv.x;
                Ks[(d + 1) * AQ_LD + row] = kv.y;
                Ks[(d + 2) * AQ_LD + row] = kv.z;
                Ks[(d + 3) * AQ_LD + row] = kv.w;
                float4 vv = *(const float4*)&vsrc[d];
                *(float4*)&Vs[row * AD_LD + d] = vv;
            }
        }
        __syncthreads();

        float s[4][4];
#pragma unroll
        for (int i = 0; i < 4; i++)
#pragma unroll
            for (int j = 0; j < 4; j++) s[i][j] = 0.0f;

#pragma unroll
        for (int d = 0; d < HDIM; d++) {
            float4 a = *(const float4*)&Qs[d * AQ_LD + ty * 4];
            float4 bb = *(const float4*)&Ks[d * AQ_LD + tx * 4];
            float av[4] = {a.x, a.y, a.z, a.w};
            float bv[4] = {bb.x, bb.y, bb.z, bb.w};
#pragma unroll
            for (int i = 0; i < 4; i++)
#pragma unroll
                for (int j = 0; j < 4; j++)
                    s[i][j] = fmaf(av[i], bv[j], s[i][j]);
        }

#pragma unroll
        for (int i = 0; i < 4; i++) {
            const float4 mv = *(const float4*)&mask[((size_t)b * SEQ + q0 + ty * 4 + i) * SEQ
                                                    + kv0 + tx * 4];
            s[i][0] = fmaf(mv.x, -10000.0f, s[i][0]);
            s[i][1] = fmaf(mv.y, -10000.0f, s[i][1]);
            s[i][2] = fmaf(mv.z, -10000.0f, s[i][2]);
            s[i][3] = fmaf(mv.w, -10000.0f, s[i][3]);
        }

#pragma unroll
        for (int i = 0; i < 4; i++) {
            float rm = fmaxf(fmaxf(s[i][0], s[i][1]), fmaxf(s[i][2], s[i][3]));
#pragma unroll
            for (int o = 1; o < 16; o <<= 1)
                rm = fmaxf(rm, __shfl_xor_sync(0xffffffff, rm, o));
            float mnew = fmaxf(m_i[i], rm);
            float corr = __expf(m_i[i] - mnew);
            float rs = 0.0f;
#pragma unroll
            for (int j = 0; j < 4; j++) {
                float p = __expf(s[i][j] - mnew);
                s[i][j] = p;
                rs += p;
            }
#pragma unroll
            for (int o = 1; o < 16; o <<= 1)
                rs += __shfl_xor_sync(0xffffffff, rs, o);
            l_i[i] = l_i[i] * corr + rs;
            m_i[i] = mnew;
#pragma unroll
            for (int j = 0; j < 4; j++) acc[i][j] *= corr;
        }

#pragma unroll
        for (int i = 0; i < 4; i++) {
            float4 pv = make_float4(s[i][0], s[i][1], s[i][2], s[i][3]);
            *(float4*)&Ps[(ty * 4 + i) * AQ_LD + tx * 4] = pv;
        }
        __syncthreads();

#pragma unroll 8
        for (int j = 0; j < BKV; j++) {
            float4 bb = *(const float4*)&Vs[j * AD_LD + tx * 4];
            float a0 = Ps[(ty * 4 + 0) * AQ_LD + j];
            float a1 = Ps[(ty * 4 + 1) * AQ_LD + j];
            float a2 = Ps[(ty * 4 + 2) * AQ_LD + j];
            float a3 = Ps[(ty * 4 + 3) * AQ_LD + j];
            float bv[4] = {bb.x, bb.y, bb.z, bb.w};
            float av[4] = {a0, a1, a2, a3};
#pragma unroll
            for (int i = 0; i < 4; i++)
#pragma unroll
                for (int jj = 0; jj < 4; jj++)
                    acc[i][jj] = fmaf(av[i], bv[jj], acc[i][jj]);
        }
    }

#pragma unroll
    for (int i = 0; i < 4; i++) {
        float inv = 1.0f / l_i[i];
        float4 o = make_float4(acc[i][0] * inv, acc[i][1] * inv,
                               acc[i][2] * inv, acc[i][3] * inv);
        *(float4*)&ctx[((size_t)b * SEQ + q0 + ty * 4 + i) * EMB + h * HDIM + tx * 4] = o;
    }
}

// ---------------------------------------------------------------------------
// Launch
// ---------------------------------------------------------------------------
extern "C" void kernel_launch(void* const* d_in, const int* in_sizes, int n_in,
                              void* d_out, int out_size)
{
    const float* x     = (const float*)d_in[0];
    const float* mask  = (const float*)d_in[1];
    const float* w_in  = (const float*)d_in[2];
    const float* b_in  = (const float*)d_in[3];
    const float* w_out = (const float*)d_in[4];
    const float* b_out = (const float*)d_in[5];
    float* out = (float*)d_out;

    void* pq = nullptr;
    void* pc = nullptr;
    cudaGetSymbolAddress(&pq, g_qkv);
    cudaGetSymbolAddress(&pc, g_ctx);
    float* qkv = (float*)pq;
    float* ctx = (float*)pc;

    cudaFuncSetAttribute(gemm_mma_kernel, cudaFuncAttributeMaxDynamicSharedMemorySize, GSMEM);
    const int attn_smem = (2 * HDIM * AQ_LD + BKV * AD_LD + BQ * AQ_LD) * (int)sizeof(float);
    cudaFuncSetAttribute(attn_kernel, cudaFuncAttributeMaxDynamicSharedMemorySize, attn_smem);

    // 1) QKV projection: [4096,3072] = x @ W_in^T + b_in
    {
        dim3 grid(3 * EMB / 128, MROWS / 128);
        gemm_mma_kernel<<<grid, 256, GSMEM>>>(x, w_in, b_in, qkv, MROWS, 3 * EMB, EMB);
    }

    // 2) attention -> ctx [B,S,E]
    {
        dim3 grid(SEQ / BQ, HEADS, BATCH);
        attn_kernel<<<grid, 256, attn_smem>>>(qkv, mask, ctx);
    }

    // 3) output projection
    {
        dim3 grid(EMB / 128, MROWS / 128);
        gemm_mma_kernel<<<grid, 256, GSMEM>>>(ctx, w_out, b_out, out, MROWS, EMB, EMB);
    }
}

// round 4
// speedup vs baseline: 1.3572x; 1.0026x over previous
#include <cuda_runtime.h>
#include <cuda_bf16.h>
#include <math.h>
#include <stdint.h>

// ---------------------------------------------------------------------------
// Problem constants
// ---------------------------------------------------------------------------
#define BATCH 2
#define SEQ   2048
#define EMB   1024
#define HEADS 16
#define HDIM  64
#define MROWS (BATCH * SEQ)        // 4096

// Scratch (no cudaMalloc allowed)
__device__ float g_qkv[MROWS * 3 * EMB];   // [B*S, 3E]
__device__ float g_ctx[MROWS * EMB];       // [B*S, E]

// ---------------------------------------------------------------------------
// warp-MMA helpers (sm_80+ PTX — legal under compute_103; NO tcgen05)
// ---------------------------------------------------------------------------
__device__ __forceinline__ uint32_t smem_u32(const void* p) {
    uint32_t a;
    asm("{ .reg .u64 t; cvta.to.shared.u64 t, %1; cvt.u32.u64 %0, t; }"
        : "=r"(a) : "l"(p));
    return a;
}

__device__ __forceinline__ void ldsm4(uint32_t r[4], uint32_t addr) {
    asm volatile("ldmatrix.sync.aligned.m8n8.x4.shared.b16 {%0,%1,%2,%3}, [%4];"
                 : "=r"(r[0]), "=r"(r[1]), "=r"(r[2]), "=r"(r[3]) : "r"(addr));
}

__device__ __forceinline__ void ldsm2(uint32_t r[2], uint32_t addr) {
    asm volatile("ldmatrix.sync.aligned.m8n8.x2.shared.b16 {%0,%1}, [%2];"
                 : "=r"(r[0]), "=r"(r[1]) : "r"(addr));
}

__device__ __forceinline__ void mma16816(float d[4], const uint32_t a[4], const uint32_t b[2]) {
    asm volatile(
        "mma.sync.aligned.m16n8k16.row.col.f32.bf16.bf16.f32 "
        "{%0,%1,%2,%3}, {%4,%5,%6,%7}, {%8,%9}, {%0,%1,%2,%3};"
        : "+f"(d[0]), "+f"(d[1]), "+f"(d[2]), "+f"(d[3])
        : "r"(a[0]), "r"(a[1]), "r"(a[2]), "r"(a[3]), "r"(b[0]), "r"(b[1]));
}

// ---------------------------------------------------------------------------
// Tensor-core GEMM NT (bf16 hi/lo split, fp32 accumulate):
//   C[M,N] = A[M,K] @ B[N,K]^T + bias[N]
// 128x128 CTA tile, 8 warps (2x4 grid of 64x32 warp tiles), K chunk 32,
// double-buffered smem (pitch-40 bf16 rows for conflict-free ldmatrix).
// ---------------------------------------------------------------------------
#define PITCH 40                       // bf16 elems per smem row (80B)
#define TSZ   (128 * PITCH)            // elems per tile buffer
#define TSZB  (TSZ * 2)                // bytes per tile buffer
#define STAGEB (4 * TSZB)              // Ah,Al,Bh,Bl per stage
#define GSMEM  (2 * STAGEB)            // 81920 B

__device__ __forceinline__ void cvt_store8(float4 v, __nv_bfloat16* smem_base,
                                           uint32_t elem_off) {
    __nv_bfloat162 h01 = __float22bfloat162_rn(make_float2(v.x, v.y));
    __nv_bfloat162 h23 = __float22bfloat162_rn(make_float2(v.z, v.w));
    float2 f01 = __bfloat1622float2(h01);
    float2 f23 = __bfloat1622float2(h23);
    __nv_bfloat162 l01 = __float22bfloat162_rn(make_float2(v.x - f01.x, v.y - f01.y));
    __nv_bfloat162 l23 = __float22bfloat162_rn(make_float2(v.z - f23.x, v.w - f23.y));
    // hi at elem_off, lo at elem_off + TSZ
    uint2 hv, lv;
    hv.x = *(uint32_t*)&h01; hv.y = *(uint32_t*)&h23;
    lv.x = *(uint32_t*)&l01; lv.y = *(uint32_t*)&l23;
    *(uint2*)(smem_base + elem_off)       = hv;
    *(uint2*)(smem_base + elem_off + TSZ) = lv;
}

__global__ void __launch_bounds__(256, 1)
gemm_mma_kernel(const float* __restrict__ A,
                const float* __restrict__ B,
                const float* __restrict__ bias,
                float* __restrict__ C,
                int M, int N, int K)
{
    extern __shared__ __nv_bfloat16 smem[];
    const uint32_t sb = smem_u32(smem);

    const int tid  = threadIdx.x;
    const int lane = tid & 31;
    const int warp = tid >> 5;
    const int wm   = warp & 1;          // 0..1  (M)
    const int wn   = warp >> 1;         // 0..3  (N)
    const int m0   = blockIdx.y * 128;
    const int n0   = blockIdx.x * 128;

    float acc[4][4][4];
#pragma unroll
    for (int mi = 0; mi < 4; mi++)
#pragma unroll
        for (int ni = 0; ni < 4; ni++)
#pragma unroll
            for (int f = 0; f < 4; f++) acc[mi][ni][f] = 0.0f;

    // per-thread global-load geometry: 4 float4 each for A and B per chunk
    int lrow[4], lcol[4];
#pragma unroll
    for (int i = 0; i < 4; i++) {
        int idx = tid + i * 256;       // 0..1023
        lrow[i] = idx >> 3;            // 0..127
        lcol[i] = (idx & 7) * 4;       // 0..28
    }

    const int nch = K / 32;
    float4 ra[4], rb[4];

    // prologue: chunk 0
#pragma unroll
    for (int i = 0; i < 4; i++) {
        ra[i] = *(const float4*)(A + (size_t)(m0 + lrow[i]) * K + lcol[i]);
        rb[i] = *(const float4*)(B + (size_t)(n0 + lrow[i]) * K + lcol[i]);
    }
    {
        __nv_bfloat16* st = smem;      // stage 0
#pragma unroll
        for (int i = 0; i < 4; i++) {
            uint32_t off = lrow[i] * PITCH + lcol[i];
            cvt_store8(ra[i], st, off);                 // Ah/Al
            cvt_store8(rb[i], st + 2 * TSZ, off);       // Bh/Bl
        }
    }
    __syncthreads();

    // fragment addressing (stage-relative, bytes)
    const int arow  = lane & 15;
    const int acolb = (lane >> 4) * 8;          // 0 or 8 elems
    const int brow  = lane & 7;
    const int bcolb = ((lane >> 3) & 1) * 8;    // 0 or 8 elems

    for (int c = 0; c < nch; c++) {
        // issue next chunk's global loads (overlap with MMA below)
        if (c + 1 < nch) {
            const float* Ap = A + (size_t)m0 * K + (c + 1) * 32;
            const float* Bp = B + (size_t)n0 * K + (c + 1) * 32;
#pragma unroll
            for (int i = 0; i < 4; i++) {
                ra[i] = *(const float4*)(Ap + (size_t)lrow[i] * K + lcol[i]);
                rb[i] = *(const float4*)(Bp + (size_t)lrow[i] * K + lcol[i]);
            }
        }

        // compute chunk c from stage c&1
        const uint32_t stg = sb + (uint32_t)(c & 1) * STAGEB;
#pragma unroll
        for (int ks = 0; ks < 2; ks++) {
            uint32_t ah[4][4], al[4][4];
            const uint32_t acol = ks * 16 + acolb;
#pragma unroll
            for (int mi = 0; mi < 4; mi++) {
                uint32_t ad = stg + ((wm * 64 + mi * 16 + arow) * PITCH + acol) * 2;
                ldsm4(ah[mi], ad);
                ldsm4(al[mi], ad + TSZB);
            }
            const uint32_t bcol = ks * 16 + bcolb;
#pragma unroll
            for (int ni = 0; ni < 4; ni++) {
                uint32_t bd = stg + 2 * TSZB + ((wn * 32 + ni * 8 + brow) * PITCH + bcol) * 2;
                uint32_t bh[2], bl[2];
                ldsm2(bh, bd);
                ldsm2(bl, bd + TSZB);
#pragma unroll
                for (int mi = 0; mi < 4; mi++) {
                    mma16816(acc[mi][ni], ah[mi], bh);
                    mma16816(acc[mi][ni], ah[mi], bl);
                    mma16816(acc[mi][ni], al[mi], bh);
                }
            }
        }

        // store next chunk into the other stage
        if (c + 1 < nch) {
            __nv_bfloat16* st = smem + ((c + 1) & 1) * (STAGEB / 2);
#pragma unroll
            for (int i = 0; i < 4; i++) {
                uint32_t off = lrow[i] * PITCH + lcol[i];
                cvt_store8(ra[i], st, off);
                cvt_store8(rb[i], st + 2 * TSZ, off);
            }
            __syncthreads();
        }
    }

    // epilogue: fragment layout d0,d1 -> row l/4, cols 2*(l%4); d2,d3 -> row+8
    const int erow = lane >> 2;
    const int ecol = (lane & 3) * 2;
#pragma unroll
    for (int mi = 0; mi < 4; mi++) {
        int r0 = m0 + wm * 64 + mi * 16 + erow;
#pragma unroll
        for (int ni = 0; ni < 4; ni++) {
            int cc = n0 + wn * 32 + ni * 8 + ecol;
            float b0 = bias[cc], b1 = bias[cc + 1];
            float2 v0 = make_float2(acc[mi][ni][0] + b0, acc[mi][ni][1] + b1);
            float2 v1 = make_float2(acc[mi][ni][2] + b0, acc[mi][ni][3] + b1);
            *(float2*)(C + (size_t)r0 * N + cc)       = v0;
            *(float2*)(C + (size_t)(r0 + 8) * N + cc) = v1;
        }
    }
}

// ---------------------------------------------------------------------------
// Flash attention (fp32) — unchanged from round 1 (passing)
// ---------------------------------------------------------------------------
#define BQ  64
#define BKV 64
#define APAD 4
#define AQ_LD (BQ + APAD)
#define AD_LD (HDIM + APAD)

__global__ __launch_bounds__(256, 2)
void attn_kernel(const float* __restrict__ qkv,
                 const float* __restrict__ mask,
                 float* __restrict__ ctx)
{
    extern __shared__ float sm[];
    float* Qs = sm;
    float* Ks = Qs + HDIM * AQ_LD;
    float* Vs = Ks + HDIM * AQ_LD;
    float* Ps = Vs + BKV * AD_LD;

    const int qt = blockIdx.x;
    const int h  = blockIdx.y;
    const int b  = blockIdx.z;
    const int tid = threadIdx.x;
    const int tx  = tid & 15;
    const int ty  = tid >> 4;

    const int q0 = qt * BQ;
    const float scale = 0.125f;
    const size_t rowstride = 3 * EMB;
    const float* qbase = qkv + (size_t)b * SEQ * rowstride + h * HDIM;
    const float* kbase = qbase + EMB;
    const float* vbase = qbase + 2 * EMB;

    {
        int row = tid >> 2;
        int c0  = (tid & 3) * 16;
        const float* src = qbase + (size_t)(q0 + row) * rowstride;
#pragma unroll
        for (int c = 0; c < 4; c++) {
            float4 v = *(const float4*)&src[c0 + c * 4];
            int d = c0 + c * 4;
            Qs[(d + 0) * AQ_LD + row] = v.x * scale;
            Qs[(d + 1) * AQ_LD + row] = v.y * scale;
            Qs[(d + 2) * AQ_LD + row] = v.z * scale;
            Qs[(d + 3) * AQ_LD + row] = v.w * scale;
        }
    }

    float m_i[4], l_i[4], acc[4][4];
#pragma unroll
    for (int i = 0; i < 4; i++) {
        m_i[i] = -INFINITY;
        l_i[i] = 0.0f;
#pragma unroll
        for (int j = 0; j < 4; j++) acc[i][j] = 0.0f;
    }

    for (int kv0 = 0; kv0 < SEQ; kv0 += BKV) {
        __syncthreads();
        {
            int row = tid >> 2;
            int c0  = (tid & 3) * 16;
            const float* ksrc = kbase + (size_t)(kv0 + row) * rowstride;
            const float* vsrc = vbase + (size_t)(kv0 + row) * rowstride;
#pragma unroll
            for (int c = 0; c < 4; c++) {
                int d = c0 + c * 4;
                float4 kv = *(const float4*)&ksrc[d];
                Ks[(d + 0) * AQ_LD + row] = kv.x;
                Ks[(d + 1) * AQ_LD + row] = kv.y;
                Ks[(d + 2) * AQ_LD + row] = kv.z;
                Ks[(d + 3) * AQ_LD + row] = kv.w;
                float4 vv = *(const float4*)&vsrc[d];
                *(float4*)&Vs[row * AD_LD + d] = vv;
            }
        }
        __syncthreads();

        float s[4][4];
#pragma unroll
        for (int i = 0; i < 4; i++)
#pragma unroll
            for (int j = 0; j < 4; j++) s[i][j] = 0.0f;

#pragma unroll
        for (int d = 0; d < HDIM; d++) {
            float4 a = *(const float4*)&Qs[d * AQ_LD + ty * 4];
            float4 bb = *(const float4*)&Ks[d * AQ_LD + tx * 4];
            float av[4] = {a.x, a.y, a.z, a.w};
            float bv[4] = {bb.x, bb.y, bb.z, bb.w};
#pragma unroll
            for (int i = 0; i < 4; i++)
#pragma unroll
                for (int j = 0; j < 4; j++)
                    s[i][j] = fmaf(av[i], bv[j], s[i][j]);
        }

#pragma unroll
        for (int i = 0; i < 4; i++) {
            const float4 mv = *(const float4*)&mask[((size_t)b * SEQ + q0 + ty * 4 + i) * SEQ
                                                    + kv0 + tx * 4];
            s[i][0] = fmaf(mv.x, -10000.0f, s[i][0]);
            s[i][1] = fmaf(mv.y, -10000.0f, s[i][1]);
            s[i][2] = fmaf(mv.z, -10000.0f, s[i][2]);
            s[i][3] = fmaf(mv.w, -10000.0f, s[i][3]);
        }

#pragma unroll
        for (int i = 0; i < 4; i++) {
            float rm = fmaxf(fmaxf(s[i][0], s[i][1]), fmaxf(s[i][2], s[i][3]));
#pragma unroll
            for (int o = 1; o < 16; o <<= 1)
                rm = fmaxf(rm, __shfl_xor_sync(0xffffffff, rm, o));
            float mnew = fmaxf(m_i[i], rm);
            float corr = __expf(m_i[i] - mnew);
            float rs = 0.0f;
#pragma unroll
            for (int j = 0; j < 4; j++) {
                float p = __expf(s[i][j] - mnew);
                s[i][j] = p;
                rs += p;
            }
#pragma unroll
            for (int o = 1; o < 16; o <<= 1)
                rs += __shfl_xor_sync(0xffffffff, rs, o);
            l_i[i] = l_i[i] * corr + rs;
            m_i[i] = mnew;
#pragma unroll
            for (int j = 0; j < 4; j++) acc[i][j] *= corr;
        }

#pragma unroll
        for (int i = 0; i < 4; i++) {
            float4 pv = make_float4(s[i][0], s[i][1], s[i][2], s[i][3]);
            *(float4*)&Ps[(ty * 4 + i) * AQ_LD + tx * 4] = pv;
        }
        __syncthreads();

#pragma unroll 8
        for (int j = 0; j < BKV; j++) {
            float4 bb = *(const float4*)&Vs[j * AD_LD + tx * 4];
            float a0 = Ps[(ty * 4 + 0) * AQ_LD + j];
            float a1 = Ps[(ty * 4 + 1) * AQ_LD + j];
            float a2 = Ps[(ty * 4 + 2) * AQ_LD + j];
            float a3 = Ps[(ty * 4 + 3) * AQ_LD + j];
            float bv[4] = {bb.x, bb.y, bb.z, bb.w};
            float av[4] = {a0, a1, a2, a3};
#pragma unroll
            for (int i = 0; i < 4; i++)
#pragma unroll
                for (int jj = 0; jj < 4; jj++)
                    acc[i][jj] = fmaf(av[i], bv[jj], acc[i][jj]);
        }
    }

#pragma unroll
    for (int i = 0; i < 4; i++) {
        float inv = 1.0f / l_i[i];
        float4 o = make_float4(acc[i][0] * inv, acc[i][1] * inv,
                               acc[i][2] * inv, acc[i][3] * inv);
        *(float4*)&ctx[((size_t)b * SEQ + q0 + ty * 4 + i) * EMB + h * HDIM + tx * 4] = o;
    }
}

// ---------------------------------------------------------------------------
// Launch
// ---------------------------------------------------------------------------
extern "C" void kernel_launch(void* const* d_in, const int* in_sizes, int n_in,
                              void* d_out, int out_size)
{
    const float* x     = (const float*)d_in[0];
    const float* mask  = (const float*)d_in[1];
    const float* w_in  = (const float*)d_in[2];
    const float* b_in  = (const float*)d_in[3];
    const float* w_out = (const float*)d_in[4];
    const float* b_out = (const float*)d_in[5];
    float* out = (float*)d_out;

    void* pq = nullptr;
    void* pc = nullptr;
    cudaGetSymbolAddress(&pq, g_qkv);
    cudaGetSymbolAddress(&pc, g_ctx);
    float* qkv = (float*)pq;
    float* ctx = (float*)pc;

    cudaFuncSetAttribute(gemm_mma_kernel, cudaFuncAttributeMaxDynamicSharedMemorySize, GSMEM);
    const int attn_smem = (2 * HDIM * AQ_LD + BKV * AD_LD + BQ * AQ_LD) * (int)sizeof(float);
    cudaFuncSetAttribute(attn_kernel, cudaFuncAttributeMaxDynamicSharedMemorySize, attn_smem);

    // 1) QKV projection: [4096,3072] = x @ W_in^T + b_in
    {
        dim3 grid(3 * EMB / 128, MROWS / 128);
        gemm_mma_kernel<<<grid, 256, GSMEM>>>(x, w_in, b_in, qkv, MROWS, 3 * EMB, EMB);
    }

    // 2) attention -> ctx [B,S,E]
    {
        dim3 grid(SEQ / BQ, HEADS, BATCH);
        attn_kernel<<<grid, 256, attn_smem>>>(qkv, mask, ctx);
    }

    // 3) output projection
    {
        dim3 grid(EMB / 128, MROWS / 128);
        gemm_mma_kernel<<<grid, 256, GSMEM>>>(ctx, w_out, b_out, out, MROWS, EMB, EMB);
    }
}

// round 5
// speedup vs baseline: 2.5605x; 1.8866x over previous
#include <cuda_runtime.h>
#include <cuda_bf16.h>
#include <math.h>
#include <stdint.h>

// ---------------------------------------------------------------------------
// Problem constants
// ---------------------------------------------------------------------------
#define BATCH 2
#define SEQ   2048
#define EMB   1024
#define HEADS 16
#define HDIM  64
#define MROWS (BATCH * SEQ)        // 4096

__device__ float g_qkv[MROWS * 3 * EMB];   // [B*S, 3E]
__device__ float g_ctx[MROWS * EMB];       // [B*S, E]

// ---------------------------------------------------------------------------
// warp-MMA helpers (sm_80+ PTX — legal under compute_103; NO tcgen05)
// ---------------------------------------------------------------------------
__device__ __forceinline__ uint32_t smem_u32(const void* p) {
    uint32_t a;
    asm("{ .reg .u64 t; cvta.to.shared.u64 t, %1; cvt.u32.u64 %0, t; }"
        : "=r"(a) : "l"(p));
    return a;
}

__device__ __forceinline__ void ldsm4(uint32_t r[4], uint32_t addr) {
    asm volatile("ldmatrix.sync.aligned.m8n8.x4.shared.b16 {%0,%1,%2,%3}, [%4];"
                 : "=r"(r[0]), "=r"(r[1]), "=r"(r[2]), "=r"(r[3]) : "r"(addr));
}

__device__ __forceinline__ void ldsm4t(uint32_t r[4], uint32_t addr) {
    asm volatile("ldmatrix.sync.aligned.m8n8.x4.trans.shared.b16 {%0,%1,%2,%3}, [%4];"
                 : "=r"(r[0]), "=r"(r[1]), "=r"(r[2]), "=r"(r[3]) : "r"(addr));
}

__device__ __forceinline__ void ldsm2(uint32_t r[2], uint32_t addr) {
    asm volatile("ldmatrix.sync.aligned.m8n8.x2.shared.b16 {%0,%1}, [%2];"
                 : "=r"(r[0]), "=r"(r[1]) : "r"(addr));
}

__device__ __forceinline__ void mma16816(float d[4], const uint32_t a[4], const uint32_t b[2]) {
    asm volatile(
        "mma.sync.aligned.m16n8k16.row.col.f32.bf16.bf16.f32 "
        "{%0,%1,%2,%3}, {%4,%5,%6,%7}, {%8,%9}, {%0,%1,%2,%3};"
        : "+f"(d[0]), "+f"(d[1]), "+f"(d[2]), "+f"(d[3])
        : "r"(a[0]), "r"(a[1]), "r"(a[2]), "r"(a[3]), "r"(b[0]), "r"(b[1]));
}

__device__ __forceinline__ float ex2f(float x) {
    float y;
    asm("ex2.approx.f32 %0, %1;" : "=f"(y) : "f"(x));
    return y;
}

// split a pair of floats into hi/lo bf16x2 words
__device__ __forceinline__ void split_pack(float a, float b, uint32_t& h, uint32_t& l) {
    __nv_bfloat162 hh = __float22bfloat162_rn(make_float2(a, b));
    float2 f = __bfloat1622float2(hh);
    __nv_bfloat162 ll = __float22bfloat162_rn(make_float2(a - f.x, b - f.y));
    h = *(uint32_t*)&hh;
    l = *(uint32_t*)&ll;
}

// ---------------------------------------------------------------------------
// GEMM NT (bf16 hi/lo split, fp32 accumulate) — unchanged from round 4 (WIN)
// ---------------------------------------------------------------------------
#define PITCH 40
#define TSZ   (128 * PITCH)
#define TSZB  (TSZ * 2)
#define STAGEB (4 * TSZB)
#define GSMEM  (2 * STAGEB)

__device__ __forceinline__ void cvt_store8(float4 v, __nv_bfloat16* smem_base,
                                           uint32_t elem_off) {
    __nv_bfloat162 h01 = __float22bfloat162_rn(make_float2(v.x, v.y));
    __nv_bfloat162 h23 = __float22bfloat162_rn(make_float2(v.z, v.w));
    float2 f01 = __bfloat1622float2(h01);
    float2 f23 = __bfloat1622float2(h23);
    __nv_bfloat162 l01 = __float22bfloat162_rn(make_float2(v.x - f01.x, v.y - f01.y));
    __nv_bfloat162 l23 = __float22bfloat162_rn(make_float2(v.z - f23.x, v.w - f23.y));
    uint2 hv, lv;
    hv.x = *(uint32_t*)&h01; hv.y = *(uint32_t*)&h23;
    lv.x = *(uint32_t*)&l01; lv.y = *(uint32_t*)&l23;
    *(uint2*)(smem_base + elem_off)       = hv;
    *(uint2*)(smem_base + elem_off + TSZ) = lv;
}

__global__ void __launch_bounds__(256, 1)
gemm_mma_kernel(const float* __restrict__ A,
                const float* __restrict__ B,
                const float* __restrict__ bias,
                float* __restrict__ C,
                int M, int N, int K)
{
    extern __shared__ __nv_bfloat16 smem[];
    const uint32_t sb = smem_u32(smem);

    const int tid  = threadIdx.x;
    const int lane = tid & 31;
    const int warp = tid >> 5;
    const int wm   = warp & 1;
    const int wn   = warp >> 1;
    const int m0   = blockIdx.y * 128;
    const int n0   = blockIdx.x * 128;

    float acc[4][4][4];
#pragma unroll
    for (int mi = 0; mi < 4; mi++)
#pragma unroll
        for (int ni = 0; ni < 4; ni++)
#pragma unroll
            for (int f = 0; f < 4; f++) acc[mi][ni][f] = 0.0f;

    int lrow[4], lcol[4];
#pragma unroll
    for (int i = 0; i < 4; i++) {
        int idx = tid + i * 256;
        lrow[i] = idx >> 3;
        lcol[i] = (idx & 7) * 4;
    }

    const int nch = K / 32;
    float4 ra[4], rb[4];

#pragma unroll
    for (int i = 0; i < 4; i++) {
        ra[i] = *(const float4*)(A + (size_t)(m0 + lrow[i]) * K + lcol[i]);
        rb[i] = *(const float4*)(B + (size_t)(n0 + lrow[i]) * K + lcol[i]);
    }
    {
        __nv_bfloat16* st = smem;
#pragma unroll
        for (int i = 0; i < 4; i++) {
            uint32_t off = lrow[i] * PITCH + lcol[i];
            cvt_store8(ra[i], st, off);
            cvt_store8(rb[i], st + 2 * TSZ, off);
        }
    }
    __syncthreads();

    const int arow  = lane & 15;
    const int acolb = (lane >> 4) * 8;
    const int brow  = lane & 7;
    const int bcolb = ((lane >> 3) & 1) * 8;

    for (int c = 0; c < nch; c++) {
        if (c + 1 < nch) {
            const float* Ap = A + (size_t)m0 * K + (c + 1) * 32;
            const float* Bp = B + (size_t)n0 * K + (c + 1) * 32;
#pragma unroll
            for (int i = 0; i < 4; i++) {
                ra[i] = *(const float4*)(Ap + (size_t)lrow[i] * K + lcol[i]);
                rb[i] = *(const float4*)(Bp + (size_t)lrow[i] * K + lcol[i]);
            }
        }

        const uint32_t stg = sb + (uint32_t)(c & 1) * STAGEB;
#pragma unroll
        for (int ks = 0; ks < 2; ks++) {
            uint32_t ah[4][4], al[4][4];
            const uint32_t acol = ks * 16 + acolb;
#pragma unroll
            for (int mi = 0; mi < 4; mi++) {
                uint32_t ad = stg + ((wm * 64 + mi * 16 + arow) * PITCH + acol) * 2;
                ldsm4(ah[mi], ad);
                ldsm4(al[mi], ad + TSZB);
            }
            const uint32_t bcol = ks * 16 + bcolb;
#pragma unroll
            for (int ni = 0; ni < 4; ni++) {
                uint32_t bd = stg + 2 * TSZB + ((wn * 32 + ni * 8 + brow) * PITCH + bcol) * 2;
                uint32_t bh[2], bl[2];
                ldsm2(bh, bd);
                ldsm2(bl, bd + TSZB);
#pragma unroll
                for (int mi = 0; mi < 4; mi++) {
                    mma16816(acc[mi][ni], ah[mi], bh);
                    mma16816(acc[mi][ni], ah[mi], bl);
                    mma16816(acc[mi][ni], al[mi], bh);
                }
            }
        }

        if (c + 1 < nch) {
            __nv_bfloat16* st = smem + ((c + 1) & 1) * (STAGEB / 2);
#pragma unroll
            for (int i = 0; i < 4; i++) {
                uint32_t off = lrow[i] * PITCH + lcol[i];
                cvt_store8(ra[i], st, off);
                cvt_store8(rb[i], st + 2 * TSZ, off);
            }
            __syncthreads();
        }
    }

    const int erow = lane >> 2;
    const int ecol = (lane & 3) * 2;
#pragma unroll
    for (int mi = 0; mi < 4; mi++) {
        int r0 = m0 + wm * 64 + mi * 16 + erow;
#pragma unroll
        for (int ni = 0; ni < 4; ni++) {
            int cc = n0 + wn * 32 + ni * 8 + ecol;
            float b0 = bias[cc], b1 = bias[cc + 1];
            float2 v0 = make_float2(acc[mi][ni][0] + b0, acc[mi][ni][1] + b1);
            float2 v1 = make_float2(acc[mi][ni][2] + b0, acc[mi][ni][3] + b1);
            *(float2*)(C + (size_t)r0 * N + cc)       = v0;
            *(float2*)(C + (size_t)(r0 + 8) * N + cc) = v1;
        }
    }
}

// ---------------------------------------------------------------------------
// Flash attention via mma.sync bf16 hi/lo split, fp32 accumulate.
// CTA = 128 queries x one (b,h). 8 warps x 16 query rows. KV tiles of 64,
// double-buffered K/V smem + register prefetch. Softmax in log2 domain.
// ---------------------------------------------------------------------------
#define ABQ  128
#define ABKV 64
#define APITCH 72                            // bf16 elems per smem row (144B)

// smem layout (bf16 elems)
#define Q_H   0
#define Q_L   (128 * APITCH)                 // 9216
#define KV0   (2 * 128 * APITCH)             // 18432; per stage:
#define KS_H  0
#define KS_L  (64 * APITCH)                  // 4608
#define VS_H  (2 * 64 * APITCH)              // 9216
#define VS_L  (3 * 64 * APITCH)              // 13824
#define KVSTG (4 * 64 * APITCH)              // 18432 elems per stage
#define ASMEM ((KV0 + 2 * KVSTG) * 2)        // 110592 bytes

#define QK_SCALE (0.125f * 1.44269504089f)   // 1/sqrt(64) * log2(e)
#define MASK_C   (-14426.950408f)            // -10000 * log2(e)

__device__ __forceinline__ void cvt_split_store4(float4 v, __nv_bfloat16* base,
                                                 uint32_t off_h, uint32_t off_l) {
    __nv_bfloat162 h01 = __float22bfloat162_rn(make_float2(v.x, v.y));
    __nv_bfloat162 h23 = __float22bfloat162_rn(make_float2(v.z, v.w));
    float2 f01 = __bfloat1622float2(h01);
    float2 f23 = __bfloat1622float2(h23);
    __nv_bfloat162 l01 = __float22bfloat162_rn(make_float2(v.x - f01.x, v.y - f01.y));
    __nv_bfloat162 l23 = __float22bfloat162_rn(make_float2(v.z - f23.x, v.w - f23.y));
    uint2 hv, lv;
    hv.x = *(uint32_t*)&h01; hv.y = *(uint32_t*)&h23;
    lv.x = *(uint32_t*)&l01; lv.y = *(uint32_t*)&l23;
    *(uint2*)(base + off_h) = hv;
    *(uint2*)(base + off_l) = lv;
}

__global__ void __launch_bounds__(256, 1)
attn_mma_kernel(const float* __restrict__ qkv,
                const float* __restrict__ mask,
                float* __restrict__ ctx)
{
    extern __shared__ __nv_bfloat16 smem[];
    const uint32_t sb = smem_u32(smem);

    const int tid  = threadIdx.x;
    const int lane = tid & 31;
    const int warp = tid >> 5;
    const int qt = blockIdx.x;
    const int h  = blockIdx.y;
    const int b  = blockIdx.z;
    const int q0 = qt * ABQ;

    const size_t rowstride = 3 * EMB;
    const float* qbase = qkv + ((size_t)b * SEQ) * rowstride + h * HDIM;
    const float* kbase = qbase + EMB;
    const float* vbase = qbase + 2 * EMB;

    // ---- load Q (scaled by QK_SCALE), split hi/lo into smem ----
#pragma unroll
    for (int i = 0; i < 8; i++) {
        int idx = tid + i * 256;             // 0..2047
        int row = idx >> 4;                  // 0..127
        int c4  = (idx & 15) * 4;            // 0..60
        float4 v = *(const float4*)(qbase + (size_t)(q0 + row) * rowstride + c4);
        v.x *= QK_SCALE; v.y *= QK_SCALE; v.z *= QK_SCALE; v.w *= QK_SCALE;
        uint32_t off = row * APITCH + c4;
        cvt_split_store4(v, smem, Q_H + off, Q_L + off);
    }

    // ---- prologue: load KV tile 0 into regs, store stage 0 ----
    int krow4[4], kcol4[4];
#pragma unroll
    for (int i = 0; i < 4; i++) {
        int idx = tid + i * 256;             // 0..1023
        krow4[i] = idx >> 4;                 // 0..63
        kcol4[i] = (idx & 15) * 4;
    }
    float4 rk[4], rv[4];
#pragma unroll
    for (int i = 0; i < 4; i++) {
        rk[i] = *(const float4*)(kbase + (size_t)krow4[i] * rowstride + kcol4[i]);
        rv[i] = *(const float4*)(vbase + (size_t)krow4[i] * rowstride + kcol4[i]);
    }
    {
        __nv_bfloat16* st = smem + KV0;      // stage 0
#pragma unroll
        for (int i = 0; i < 4; i++) {
            uint32_t off = krow4[i] * APITCH + kcol4[i];
            cvt_split_store4(rk[i], st, KS_H + off, KS_L + off);
            cvt_split_store4(rv[i], st, VS_H + off, VS_L + off);
        }
    }
    __syncthreads();

    // ---- preload Q fragments (persistent across kv loop) ----
    uint32_t qh[4][4], ql[4][4];
    {
        const int arow  = warp * 16 + (lane & 15);
        const int acolb = (lane >> 4) * 8;
#pragma unroll
        for (int ks = 0; ks < 4; ks++) {
            uint32_t ad = sb + (arow * APITCH + ks * 16 + acolb) * 2;
            ldsm4(qh[ks], ad);
            ldsm4(ql[ks], ad + Q_L * 2);
        }
    }

    // ---- state ----
    float o[8][4];
#pragma unroll
    for (int nt = 0; nt < 8; nt++)
#pragma unroll
        for (int f = 0; f < 4; f++) o[nt][f] = 0.0f;
    float m0r = -INFINITY, m1r = -INFINITY;
    float l0r = 0.0f, l1r = 0.0f;

    // lane geometry for ldsm in loop
    const int kfrow = ((lane >> 4) & 1) * 8 + (lane & 7);       // K frag row within 16-block
    const int kfcol = ((lane >> 3) & 1) * 8;                    // K frag col offset
    const int vfrow = ((lane >> 3) & 1) * 8 + (lane & 7);       // V frag row within kstep
    const int vfcol = ((lane >> 4) & 1) * 8;                    // V frag col offset
    const float* mrow0 = mask + ((size_t)b * SEQ + q0 + warp * 16 + (lane >> 2)) * SEQ
                         + (lane & 3) * 2;
    const float* mrow1 = mrow0 + 8 * SEQ;

    const int NKV = SEQ / ABKV;              // 32
#pragma unroll 1
    for (int c = 0; c < NKV; c++) {
        // prefetch next tile
        if (c + 1 < NKV) {
            const float* kp = kbase + (size_t)(c + 1) * ABKV * rowstride;
            const float* vp = vbase + (size_t)(c + 1) * ABKV * rowstride;
#pragma unroll
            for (int i = 0; i < 4; i++) {
                rk[i] = *(const float4*)(kp + (size_t)krow4[i] * rowstride + kcol4[i]);
                rv[i] = *(const float4*)(vp + (size_t)krow4[i] * rowstride + kcol4[i]);
            }
        }

        const uint32_t stg = sb + (KV0 + (c & 1) * KVSTG) * 2;  // byte addr

        // ---- S = Qs @ K^T (hi/lo split) ----
        float s[8][4];
#pragma unroll
        for (int nt = 0; nt < 8; nt++)
#pragma unroll
            for (int f = 0; f < 4; f++) s[nt][f] = 0.0f;

#pragma unroll
        for (int ks = 0; ks < 4; ks++) {
#pragma unroll
            for (int nt2 = 0; nt2 < 4; nt2++) {
                uint32_t ka = stg + ((nt2 * 16 + kfrow) * APITCH + ks * 16 + kfcol) * 2;
                uint32_t kh4[4], kl4[4];
                ldsm4(kh4, ka);
                ldsm4(kl4, ka + KS_L * 2);
                mma16816(s[2 * nt2],     qh[ks], kh4);
                mma16816(s[2 * nt2],     qh[ks], kl4);
                mma16816(s[2 * nt2],     ql[ks], kh4);
                mma16816(s[2 * nt2 + 1], qh[ks], kh4 + 2);
                mma16816(s[2 * nt2 + 1], qh[ks], kl4 + 2);
                mma16816(s[2 * nt2 + 1], ql[ks], kh4 + 2);
            }
        }

        // ---- mask ----
        const int kvb = c * ABKV;
#pragma unroll
        for (int nt = 0; nt < 8; nt++) {
            float2 mv0 = *(const float2*)(mrow0 + kvb + nt * 8);
            float2 mv1 = *(const float2*)(mrow1 + kvb + nt * 8);
            s[nt][0] = fmaf(mv0.x, MASK_C, s[nt][0]);
            s[nt][1] = fmaf(mv0.y, MASK_C, s[nt][1]);
            s[nt][2] = fmaf(mv1.x, MASK_C, s[nt][2]);
            s[nt][3] = fmaf(mv1.y, MASK_C, s[nt][3]);
        }

        // ---- online softmax (log2 domain) ----
        float rm0 = s[0][0], rm1 = s[0][2];
#pragma unroll
        for (int nt = 0; nt < 8; nt++) {
            rm0 = fmaxf(rm0, fmaxf(s[nt][0], s[nt][1]));
            rm1 = fmaxf(rm1, fmaxf(s[nt][2], s[nt][3]));
        }
        rm0 = fmaxf(rm0, __shfl_xor_sync(0xffffffff, rm0, 1));
        rm0 = fmaxf(rm0, __shfl_xor_sync(0xffffffff, rm0, 2));
        rm1 = fmaxf(rm1, __shfl_xor_sync(0xffffffff, rm1, 1));
        rm1 = fmaxf(rm1, __shfl_xor_sync(0xffffffff, rm1, 2));

        float mn0 = fmaxf(m0r, rm0);
        float mn1 = fmaxf(m1r, rm1);
        float cr0 = ex2f(m0r - mn0);
        float cr1 = ex2f(m1r - mn1);
        m0r = mn0; m1r = mn1;

        float rs0 = 0.0f, rs1 = 0.0f;
#pragma unroll
        for (int nt = 0; nt < 8; nt++) {
            s[nt][0] = ex2f(s[nt][0] - mn0);
            s[nt][1] = ex2f(s[nt][1] - mn0);
            s[nt][2] = ex2f(s[nt][2] - mn1);
            s[nt][3] = ex2f(s[nt][3] - mn1);
            rs0 += s[nt][0] + s[nt][1];
            rs1 += s[nt][2] + s[nt][3];
        }
        rs0 += __shfl_xor_sync(0xffffffff, rs0, 1);
        rs0 += __shfl_xor_sync(0xffffffff, rs0, 2);
        rs1 += __shfl_xor_sync(0xffffffff, rs1, 1);
        rs1 += __shfl_xor_sync(0xffffffff, rs1, 2);
        l0r = l0r * cr0 + rs0;
        l1r = l1r * cr1 + rs1;

#pragma unroll
        for (int nt = 0; nt < 8; nt++) {
            o[nt][0] *= cr0; o[nt][1] *= cr0;
            o[nt][2] *= cr1; o[nt][3] *= cr1;
        }

        // ---- O += P @ V (hi/lo split; P frags from registers) ----
#pragma unroll
        for (int k2 = 0; k2 < 4; k2++) {
            uint32_t ph[4], pl[4];
            split_pack(s[2 * k2][0],     s[2 * k2][1],     ph[0], pl[0]);
            split_pack(s[2 * k2][2],     s[2 * k2][3],     ph[1], pl[1]);
            split_pack(s[2 * k2 + 1][0], s[2 * k2 + 1][1], ph[2], pl[2]);
            split_pack(s[2 * k2 + 1][2], s[2 * k2 + 1][3], ph[3], pl[3]);
#pragma unroll
            for (int dt2 = 0; dt2 < 4; dt2++) {
                uint32_t va = stg + (VS_H + (k2 * 16 + vfrow) * APITCH + dt2 * 16 + vfcol) * 2;
                uint32_t vh4[4], vl4[4];
                ldsm4t(vh4, va);
                ldsm4t(vl4, va + (VS_L - VS_H) * 2);
                mma16816(o[2 * dt2],     ph, vh4);
                mma16816(o[2 * dt2],     ph, vl4);
                mma16816(o[2 * dt2],     pl, vh4);
                mma16816(o[2 * dt2 + 1], ph, vh4 + 2);
                mma16816(o[2 * dt2 + 1], ph, vl4 + 2);
                mma16816(o[2 * dt2 + 1], pl, vh4 + 2);
            }
        }

        // ---- store next tile (other stage) ----
        if (c + 1 < NKV) {
            __nv_bfloat16* st = smem + KV0 + ((c + 1) & 1) * KVSTG;
#pragma unroll
            for (int i = 0; i < 4; i++) {
                uint32_t off = krow4[i] * APITCH + kcol4[i];
                cvt_split_store4(rk[i], st, KS_H + off, KS_L + off);
                cvt_split_store4(rv[i], st, VS_H + off, VS_L + off);
            }
            __syncthreads();
        }
    }

    // ---- epilogue ----
    const float inv0 = 1.0f / l0r;
    const float inv1 = 1.0f / l1r;
    const int r0 = q0 + warp * 16 + (lane >> 2);
    float* crow0 = ctx + ((size_t)b * SEQ + r0) * EMB + h * HDIM + (lane & 3) * 2;
    float* crow1 = crow0 + 8 * EMB;
#pragma unroll
    for (int nt = 0; nt < 8; nt++) {
        *(float2*)(crow0 + nt * 8) = make_float2(o[nt][0] * inv0, o[nt][1] * inv0);
        *(float2*)(crow1 + nt * 8) = make_float2(o[nt][2] * inv1, o[nt][3] * inv1);
    }
}

// ---------------------------------------------------------------------------
// Launch
// ---------------------------------------------------------------------------
extern "C" void kernel_launch(void* const* d_in, const int* in_sizes, int n_in,
                              void* d_out, int out_size)
{
    const float* x     = (const float*)d_in[0];
    const float* mask  = (const float*)d_in[1];
    const float* w_in  = (const float*)d_in[2];
    const float* b_in  = (const float*)d_in[3];
    const float* w_out = (const float*)d_in[4];
    const float* b_out = (const float*)d_in[5];
    float* out = (float*)d_out;

    void* pq = nullptr;
    void* pc = nullptr;
    cudaGetSymbolAddress(&pq, g_qkv);
    cudaGetSymbolAddress(&pc, g_ctx);
    float* qkv = (float*)pq;
    float* ctx = (float*)pc;

    cudaFuncSetAttribute(gemm_mma_kernel, cudaFuncAttributeMaxDynamicSharedMemorySize, GSMEM);
    cudaFuncSetAttribute(attn_mma_kernel, cudaFuncAttributeMaxDynamicSharedMemorySize, ASMEM);

    // 1) QKV projection
    {
        dim3 grid(3 * EMB / 128, MROWS / 128);
        gemm_mma_kernel<<<grid, 256, GSMEM>>>(x, w_in, b_in, qkv, MROWS, 3 * EMB, EMB);
    }

    // 2) attention -> ctx [B,S,E]
    {
        dim3 grid(SEQ / ABQ, HEADS, BATCH);
        attn_mma_kernel<<<grid, 256, ASMEM>>>(qkv, mask, ctx);
    }

    // 3) output projection
    {
        dim3 grid(EMB / 128, MROWS / 128);
        gemm_mma_kernel<<<grid, 256, GSMEM>>>(ctx, w_out, b_out, out, MROWS, EMB, EMB);
    }
}